// round 3
// baseline (speedup 1.0000x reference)
#include <cuda_runtime.h>
#include <math.h>

#define FRAME      480
#define NHALF      480
#define FREQ       481
#define NB_ERB     32
#define NB_DF      96
#define ALPHA_F    0.99f
#define ONE_MINUS_ALPHA 0.01f
#define WNORM_F    (1.0f/960.0f)
#define T_MAX      65536
#define CHUNKS     1024
#define PI_F       3.14159265358979f

// ---------------- static device scratch ----------------
__device__ float2 g_tw480[15*32];      // W_480^{l*k1}, layout [k1*32 + l]
__device__ float2 g_shtw[5*32];        // per-stage per-lane shuffle twiddles
__device__ float2 g_win2[NHALF];       // window pairs (w[2j], w[2j+1])
__device__ float2 g_rec[FREQ];         // cis(-pi*k/480)
__device__ float  g_erb[T_MAX * NB_ERB];
__device__ float  g_mag[T_MAX * NB_DF];
__device__ float  g_carryE[CHUNKS * NB_ERB];
__device__ float  g_inE[CHUNKS * NB_ERB];
__device__ float  g_carryS[CHUNKS * NB_DF];
__device__ float  g_inS[CHUNKS * NB_DF];

__constant__ int c_bandOff[NB_ERB] =
 {0,2,4,6,8,10,12,14,16,18,20,22,24,26,31,36,43,50,58,68,80,93,108,126,146,170,198,229,266,308,358,414};
__constant__ int c_bandCnt[NB_ERB] =
 {2,2,2,2,2,2,2,2,2,2,2,2,2,5,5,7,7,8,10,12,13,15,18,20,24,28,31,37,42,50,56,67};

// ---------------- complex helpers ----------------
__device__ __forceinline__ float2 cadd(float2 a, float2 b){ return make_float2(a.x+b.x, a.y+b.y); }
__device__ __forceinline__ float2 cmul(float2 a, float2 b){ return make_float2(a.x*b.x-a.y*b.y, a.x*b.y+a.y*b.x); }

__device__ __forceinline__ void dft3(const float2* v, float2* t){
    const float2 w1 = make_float2(-0.5f, -0.86602540378f);
    const float2 w2 = make_float2(-0.5f,  0.86602540378f);
    t[0] = cadd(cadd(v[0], v[1]), v[2]);
    t[1] = cadd(v[0], cadd(cmul(v[1], w1), cmul(v[2], w2)));
    t[2] = cadd(v[0], cadd(cmul(v[1], w2), cmul(v[2], w1)));
}
__device__ __forceinline__ void dft5(const float2* v, float2* t){
    const float2 w1 = make_float2( 0.30901699437f, -0.95105651630f);
    const float2 w2 = make_float2(-0.80901699437f, -0.58778525229f);
    const float2 w3 = make_float2(-0.80901699437f,  0.58778525229f);
    const float2 w4 = make_float2( 0.30901699437f,  0.95105651630f);
    t[0] = cadd(cadd(cadd(cadd(v[0],v[1]),v[2]),v[3]),v[4]);
    t[1] = cadd(v[0], cadd(cadd(cmul(v[1],w1), cmul(v[2],w2)), cadd(cmul(v[3],w3), cmul(v[4],w4))));
    t[2] = cadd(v[0], cadd(cadd(cmul(v[1],w2), cmul(v[2],w4)), cadd(cmul(v[3],w1), cmul(v[4],w3))));
    t[3] = cadd(v[0], cadd(cadd(cmul(v[1],w3), cmul(v[2],w1)), cadd(cmul(v[3],w4), cmul(v[4],w2))));
    t[4] = cadd(v[0], cadd(cadd(cmul(v[1],w4), cmul(v[2],w3)), cadd(cmul(v[3],w2), cmul(v[4],w1))));
}

// ---------------- init tables ----------------
__global__ void init_tables(){
    int tid = blockIdx.x * blockDim.x + threadIdx.x;
    int nth = gridDim.x * blockDim.x;
    for (int idx = tid; idx < 15*32; idx += nth){
        int k1 = idx / 32, l = idx % 32;
        float ang = -2.0f * PI_F * (float)(l * k1) / 480.0f;
        float sv, cv; sincosf(ang, &sv, &cv);
        g_tw480[idx] = make_float2(cv, sv);
    }
    for (int idx = tid; idx < 5*32; idx += nth){
        int j = idx / 32, l = idx % 32;
        int h = 16 >> j;
        if (l & h){
            float ang = -2.0f * PI_F * (float)(l & (h-1)) / (float)(2*h);
            float sv, cv; sincosf(ang, &sv, &cv);
            g_shtw[idx] = make_float2(cv, sv);
        } else {
            g_shtw[idx] = make_float2(1.f, 0.f);
        }
    }
    for (int j = tid; j < NHALF; j += nth){
        float a0 = sinf(0.5f * PI_F * (2*j + 0.5f) / 480.0f);
        float a1 = sinf(0.5f * PI_F * (2*j + 1.5f) / 480.0f);
        g_win2[j] = make_float2(sinf(0.5f * PI_F * a0 * a0), sinf(0.5f * PI_F * a1 * a1));
    }
    for (int k = tid; k < FREQ; k += nth){
        float ang = -PI_F * (float)k / 480.0f;
        float sv, cv; sincosf(ang, &sv, &cv);
        g_rec[k] = make_float2(cv, sv);
    }
}

// ---------------- FFT: one warp per frame, register-resident ----------------
__global__ __launch_bounds__(128) void fft_kernel(const float* __restrict__ audio,
                                                  float* __restrict__ out, int T){
    __shared__ float2 sZ[4][NHALF];
    __shared__ float  smag[4][FREQ];
    int w = threadIdx.x >> 5;
    int l = threadIdx.x & 31;
    int t = blockIdx.x * 4 + w;
    if (t >= T) return;                 // whole warp exits together

    const float2* audio2 = (const float2*)audio;
    long base2 = ((long)t - 1) * 240;   // float2 units

    // load + window: lane l takes n = l + 32m
    float2 z[15];
    #pragma unroll
    for (int m = 0; m < 15; m++){
        long i2 = base2 + l + 32*m;
        float2 x = (i2 >= 0) ? audio2[i2] : make_float2(0.f,0.f);
        float2 ww = g_win2[l + 32*m];
        z[m] = make_float2(x.x*ww.x, x.y*ww.y);
    }

    // ---- radix-15 DFT in registers: A[k1] = sum_m z[m] W15^{m k1}
    float2 B[15];
    {
        float2 G[5][3];
        #pragma unroll
        for (int b = 0; b < 5; b++){
            float2 v[3] = { z[b], z[5+b], z[10+b] };
            dft3(v, G[b]);
        }
        { // r = 0
            float2 v[5] = {G[0][0],G[1][0],G[2][0],G[3][0],G[4][0]};
            float2 o5[5]; dft5(v,o5);
            B[0]=o5[0]; B[3]=o5[1]; B[6]=o5[2]; B[9]=o5[3]; B[12]=o5[4];
        }
        { // r = 1, tw = cis(-2pi b/15)
            float2 v[5];
            v[0]=G[0][1];
            v[1]=cmul(G[1][1], make_float2( 0.91354545764f,-0.40673664308f));
            v[2]=cmul(G[2][1], make_float2( 0.66913060636f,-0.74314482548f));
            v[3]=cmul(G[3][1], make_float2( 0.30901699437f,-0.95105651630f));
            v[4]=cmul(G[4][1], make_float2(-0.10452846327f,-0.99452189537f));
            float2 o5[5]; dft5(v,o5);
            B[1]=o5[0]; B[4]=o5[1]; B[7]=o5[2]; B[10]=o5[3]; B[13]=o5[4];
        }
        { // r = 2, tw = cis(-4pi b/15)
            float2 v[5];
            v[0]=G[0][2];
            v[1]=cmul(G[1][2], make_float2( 0.66913060636f,-0.74314482548f));
            v[2]=cmul(G[2][2], make_float2(-0.10452846327f,-0.99452189537f));
            v[3]=cmul(G[3][2], make_float2(-0.80901699437f,-0.58778525229f));
            v[4]=cmul(G[4][2], make_float2(-0.97814760073f, 0.20791169082f));
            float2 o5[5]; dft5(v,o5);
            B[2]=o5[0]; B[5]=o5[1]; B[8]=o5[2]; B[11]=o5[3]; B[14]=o5[4];
        }
    }

    // ---- four-step twiddle: B[k1] *= W480^{l*k1}
    #pragma unroll
    for (int k1 = 1; k1 < 15; k1++)
        B[k1] = cmul(B[k1], g_tw480[k1*32 + l]);

    // ---- 32-pt DFT across lanes: 5 radix-2 DIF shuffle stages
    float2 twr[5];
    #pragma unroll
    for (int j = 0; j < 5; j++) twr[j] = g_shtw[j*32 + l];
    #pragma unroll
    for (int j = 0; j < 5; j++){
        int h = 16 >> j;
        float sgn = (l & h) ? -1.f : 1.f;
        float2 tw = twr[j];
        #pragma unroll
        for (int k1 = 0; k1 < 15; k1++){
            float px = __shfl_xor_sync(0xffffffffu, B[k1].x, h);
            float py = __shfl_xor_sync(0xffffffffu, B[k1].y, h);
            float2 nv = make_float2(px + sgn*B[k1].x, py + sgn*B[k1].y);
            B[k1] = cmul(nv, tw);       // tw = (1,0) on top lanes
        }
    }

    // lane l holds Z[k1 + 15*bitrev5(l)]
    int s = ((l&1)<<4) | ((l&2)<<2) | (l&4) | ((l&8)>>2) | ((l&16)>>4);
    float2* Z = sZ[w];
    #pragma unroll
    for (int k1 = 0; k1 < 15; k1++) Z[15*s + k1] = B[k1];
    __syncwarp();

    // ---- real-FFT recombination + spec write + mag
    float* mg = smag[w];
    float2* out2 = (float2*)out;
    size_t orow = (size_t)t * FREQ;
    for (int k = l; k <= 480; k += 32){
        float2 Zk = Z[(k == 480) ? 0 : k];
        float2 Zc = Z[(480 - k) % 480]; Zc.y = -Zc.y;
        float2 E = make_float2(0.5f*(Zk.x + Zc.x), 0.5f*(Zk.y + Zc.y));
        float2 D = make_float2(Zk.x - Zc.x, Zk.y - Zc.y);
        float2 O = make_float2(0.5f * D.y, -0.5f * D.x);
        float2 X = cadd(E, cmul(g_rec[k], O));
        X.x *= WNORM_F; X.y *= WNORM_F;
        out2[orow + k] = X;
        float m2 = X.x*X.x + X.y*X.y;
        mg[k] = m2;
        if (k < NB_DF) g_mag[(size_t)t * NB_DF + k] = sqrtf(m2);
    }
    __syncwarp();

    // ---- erb bands (32 lanes = 32 bands)
    {
        int st = c_bandOff[l], n = c_bandCnt[l];
        float acc = 0.0f;
        for (int q = 0; q < n; q++) acc += mg[st + q];
        g_erb[(size_t)t * NB_ERB + l] = 10.0f * log10f(acc / (float)n + 1e-10f);
    }
}

// ---------------- fused chunked scans ----------------
__global__ void pass1(int T){
    int w = blockIdx.x * blockDim.x + threadIdx.x;
    int len = T / CHUNKS;
    int totE = CHUNKS * NB_ERB;
    if (w < totE){
        int ch = w % NB_ERB, c = w / NB_ERB;
        const float* x = g_erb + (size_t)c * len * NB_ERB + ch;
        float s = 0.0f;
        for (int i = 0; i < len; i++) s = ALPHA_F * s + ONE_MINUS_ALPHA * x[i * NB_ERB];
        g_carryE[c * NB_ERB + ch] = s;
    } else if (w < totE + CHUNKS * NB_DF){
        int w2 = w - totE;
        int ch = w2 % NB_DF, c = w2 / NB_DF;
        const float* x = g_mag + (size_t)c * len * NB_DF + ch;
        float u = 0.0f;
        for (int i = 0; i < len; i++) u = ALPHA_F * u + ONE_MINUS_ALPHA * x[i * NB_DF];
        g_carryS[c * NB_DF + ch] = u;
    }
}

__global__ void pass2(int T){
    int len = T / CHUNKS;
    float m = powf(ALPHA_F, (float)len);
    int tid = threadIdx.x;
    if (tid < NB_ERB){
        float s = -60.0f - 30.0f * (float)tid / 31.0f;
        for (int c = 0; c < CHUNKS; c++){
            g_inE[c * NB_ERB + tid] = s;
            s = m * s + g_carryE[c * NB_ERB + tid];
        }
    } else if (tid < NB_ERB + NB_DF){
        int ch = tid - NB_ERB;
        float u = 0.001f - 0.0009f * (float)ch / 95.0f;
        for (int c = 0; c < CHUNKS; c++){
            g_inS[c * NB_DF + ch] = u;
            u = m * u + g_carryS[c * NB_DF + ch];
        }
    }
}

__global__ void pass3(float* __restrict__ out, int T){
    int w = blockIdx.x * blockDim.x + threadIdx.x;
    int len = T / CHUNKS;
    int totE = CHUNKS * NB_ERB;
    if (w < totE){
        int ch = w % NB_ERB, c = w / NB_ERB;
        size_t erb_off = (size_t)T * 962;
        const float* x = g_erb + (size_t)c * len * NB_ERB + ch;
        float* o = out + erb_off + (size_t)c * len * NB_ERB + ch;
        float s = g_inE[c * NB_ERB + ch];
        for (int i = 0; i < len; i++){
            float xv = x[i * NB_ERB];
            s = ALPHA_F * s + ONE_MINUS_ALPHA * xv;
            o[i * NB_ERB] = (xv - s) * 0.025f;
        }
    } else if (w < totE + CHUNKS * NB_DF){
        int w2 = w - totE;
        int ch = w2 % NB_DF, c = w2 / NB_DF;
        size_t sf_off = (size_t)T * 962 + (size_t)T * NB_ERB;
        const float* mgp = g_mag + (size_t)c * len * NB_DF + ch;
        const float* sp = out + (size_t)c * len * 962 + 2 * ch;
        float* o = out + sf_off + (size_t)c * len * 192 + 2 * ch;
        float u = g_inS[c * NB_DF + ch];
        for (int i = 0; i < len; i++){
            u = ALPHA_F * u + ONE_MINUS_ALPHA * mgp[i * NB_DF];
            float r = rsqrtf(u);
            o[i * 192]     = sp[i * 962]     * r;
            o[i * 192 + 1] = sp[i * 962 + 1] * r;
        }
    }
}

// ---------------- launch ----------------
extern "C" void kernel_launch(void* const* d_in, const int* in_sizes, int n_in,
                              void* d_out, int out_size){
    const float* audio = (const float*)d_in[0];
    float* out = (float*)d_out;
    int T = in_sizes[0] / FRAME;
    if (T > T_MAX) T = T_MAX;
    int scanThreads = CHUNKS * (NB_ERB + NB_DF);

    init_tables<<<8, 256>>>();
    fft_kernel<<<(T + 3) / 4, 128>>>(audio, out, T);
    pass1<<<(scanThreads + 255) / 256, 256>>>(T);
    pass2<<<1, 128>>>(T);
    pass3<<<(scanThreads + 255) / 256, 256>>>(out, T);
}

// round 4
// speedup vs baseline: 1.9468x; 1.9468x over previous
#include <cuda_runtime.h>
#include <math.h>

#define FRAME      480
#define NHALF      480
#define FREQ       481
#define NB_ERB     32
#define NB_DF      96
#define ALPHA_F    0.99f
#define ONE_MINUS_ALPHA 0.01f
#define WNORM_F    (1.0f/960.0f)
#define T_MAX      65536
#define CHUNKS     1024
#define PI_F       3.14159265358979f

// ---------------- static device scratch ----------------
__device__ float2 g_tw480[15*32];      // W_480^{l*k1}, layout [k1*32 + l]
__device__ float2 g_shtw[5*32];        // per-stage per-lane shuffle twiddles
__device__ float2 g_win2[NHALF];       // window pairs (w[2j], w[2j+1])
__device__ float2 g_rec[FREQ];         // cis(-pi*k/480)
__device__ float  g_erb[T_MAX * NB_ERB];
__device__ float  g_mag[T_MAX * NB_DF];
__device__ float  g_carryE[CHUNKS * NB_ERB];
__device__ float  g_inE[CHUNKS * NB_ERB];
__device__ float  g_carryS[CHUNKS * NB_DF];
__device__ float  g_inS[CHUNKS * NB_DF];

__constant__ int c_bandOff[NB_ERB] =
 {0,2,4,6,8,10,12,14,16,18,20,22,24,26,31,36,43,50,58,68,80,93,108,126,146,170,198,229,266,308,358,414};
__constant__ int c_bandCnt[NB_ERB] =
 {2,2,2,2,2,2,2,2,2,2,2,2,2,5,5,7,7,8,10,12,13,15,18,20,24,28,31,37,42,50,56,67};

// ---------------- complex helpers ----------------
__device__ __forceinline__ float2 cadd(float2 a, float2 b){ return make_float2(a.x+b.x, a.y+b.y); }
__device__ __forceinline__ float2 cmul(float2 a, float2 b){ return make_float2(a.x*b.x-a.y*b.y, a.x*b.y+a.y*b.x); }

__device__ __forceinline__ void dft3(const float2* v, float2* t){
    const float2 w1 = make_float2(-0.5f, -0.86602540378f);
    const float2 w2 = make_float2(-0.5f,  0.86602540378f);
    t[0] = cadd(cadd(v[0], v[1]), v[2]);
    t[1] = cadd(v[0], cadd(cmul(v[1], w1), cmul(v[2], w2)));
    t[2] = cadd(v[0], cadd(cmul(v[1], w2), cmul(v[2], w1)));
}
__device__ __forceinline__ void dft5(const float2* v, float2* t){
    const float2 w1 = make_float2( 0.30901699437f, -0.95105651630f);
    const float2 w2 = make_float2(-0.80901699437f, -0.58778525229f);
    const float2 w3 = make_float2(-0.80901699437f,  0.58778525229f);
    const float2 w4 = make_float2( 0.30901699437f,  0.95105651630f);
    t[0] = cadd(cadd(cadd(cadd(v[0],v[1]),v[2]),v[3]),v[4]);
    t[1] = cadd(v[0], cadd(cadd(cmul(v[1],w1), cmul(v[2],w2)), cadd(cmul(v[3],w3), cmul(v[4],w4))));
    t[2] = cadd(v[0], cadd(cadd(cmul(v[1],w2), cmul(v[2],w4)), cadd(cmul(v[3],w1), cmul(v[4],w3))));
    t[3] = cadd(v[0], cadd(cadd(cmul(v[1],w3), cmul(v[2],w1)), cadd(cmul(v[3],w4), cmul(v[4],w2))));
    t[4] = cadd(v[0], cadd(cadd(cmul(v[1],w4), cmul(v[2],w3)), cadd(cmul(v[3],w2), cmul(v[4],w1))));
}

// ---------------- init tables ----------------
__global__ void init_tables(){
    int tid = blockIdx.x * blockDim.x + threadIdx.x;
    int nth = gridDim.x * blockDim.x;
    for (int idx = tid; idx < 15*32; idx += nth){
        int k1 = idx / 32, l = idx % 32;
        float ang = -2.0f * PI_F * (float)(l * k1) / 480.0f;
        float sv, cv; sincosf(ang, &sv, &cv);
        g_tw480[idx] = make_float2(cv, sv);
    }
    for (int idx = tid; idx < 5*32; idx += nth){
        int j = idx / 32, l = idx % 32;
        int h = 16 >> j;
        if (l & h){
            float ang = -2.0f * PI_F * (float)(l & (h-1)) / (float)(2*h);
            float sv, cv; sincosf(ang, &sv, &cv);
            g_shtw[idx] = make_float2(cv, sv);
        } else {
            g_shtw[idx] = make_float2(1.f, 0.f);
        }
    }
    for (int j = tid; j < NHALF; j += nth){
        float a0 = sinf(0.5f * PI_F * (2*j + 0.5f) / 480.0f);
        float a1 = sinf(0.5f * PI_F * (2*j + 1.5f) / 480.0f);
        g_win2[j] = make_float2(sinf(0.5f * PI_F * a0 * a0), sinf(0.5f * PI_F * a1 * a1));
    }
    for (int k = tid; k < FREQ; k += nth){
        float ang = -PI_F * (float)k / 480.0f;
        float sv, cv; sincosf(ang, &sv, &cv);
        g_rec[k] = make_float2(cv, sv);
    }
}

// ---------------- FFT: one warp per frame, register-resident ----------------
__global__ __launch_bounds__(128) void fft_kernel(const float* __restrict__ audio,
                                                  float* __restrict__ out, int T){
    __shared__ float2 sZ[4][NHALF];
    __shared__ float  smag[4][FREQ];
    int w = threadIdx.x >> 5;
    int l = threadIdx.x & 31;
    int t = blockIdx.x * 4 + w;
    if (t >= T) return;                 // whole warp exits together

    const float2* audio2 = (const float2*)audio;
    long base2 = ((long)t - 1) * 240;   // float2 units

    // load + window: lane l takes n = l + 32m
    float2 z[15];
    #pragma unroll
    for (int m = 0; m < 15; m++){
        long i2 = base2 + l + 32*m;
        float2 x = (i2 >= 0) ? audio2[i2] : make_float2(0.f,0.f);
        float2 ww = g_win2[l + 32*m];
        z[m] = make_float2(x.x*ww.x, x.y*ww.y);
    }

    // ---- radix-15 DFT in registers
    float2 B[15];
    {
        float2 G[5][3];
        #pragma unroll
        for (int b = 0; b < 5; b++){
            float2 v[3] = { z[b], z[5+b], z[10+b] };
            dft3(v, G[b]);
        }
        {
            float2 v[5] = {G[0][0],G[1][0],G[2][0],G[3][0],G[4][0]};
            float2 o5[5]; dft5(v,o5);
            B[0]=o5[0]; B[3]=o5[1]; B[6]=o5[2]; B[9]=o5[3]; B[12]=o5[4];
        }
        {
            float2 v[5];
            v[0]=G[0][1];
            v[1]=cmul(G[1][1], make_float2( 0.91354545764f,-0.40673664308f));
            v[2]=cmul(G[2][1], make_float2( 0.66913060636f,-0.74314482548f));
            v[3]=cmul(G[3][1], make_float2( 0.30901699437f,-0.95105651630f));
            v[4]=cmul(G[4][1], make_float2(-0.10452846327f,-0.99452189537f));
            float2 o5[5]; dft5(v,o5);
            B[1]=o5[0]; B[4]=o5[1]; B[7]=o5[2]; B[10]=o5[3]; B[13]=o5[4];
        }
        {
            float2 v[5];
            v[0]=G[0][2];
            v[1]=cmul(G[1][2], make_float2( 0.66913060636f,-0.74314482548f));
            v[2]=cmul(G[2][2], make_float2(-0.10452846327f,-0.99452189537f));
            v[3]=cmul(G[3][2], make_float2(-0.80901699437f,-0.58778525229f));
            v[4]=cmul(G[4][2], make_float2(-0.97814760073f, 0.20791169082f));
            float2 o5[5]; dft5(v,o5);
            B[2]=o5[0]; B[5]=o5[1]; B[8]=o5[2]; B[11]=o5[3]; B[14]=o5[4];
        }
    }

    // ---- four-step twiddle: B[k1] *= W480^{l*k1}
    #pragma unroll
    for (int k1 = 1; k1 < 15; k1++)
        B[k1] = cmul(B[k1], g_tw480[k1*32 + l]);

    // ---- 32-pt DFT across lanes: 5 radix-2 DIF shuffle stages
    float2 twr[5];
    #pragma unroll
    for (int j = 0; j < 5; j++) twr[j] = g_shtw[j*32 + l];
    #pragma unroll
    for (int j = 0; j < 5; j++){
        int h = 16 >> j;
        float sgn = (l & h) ? -1.f : 1.f;
        float2 tw = twr[j];
        #pragma unroll
        for (int k1 = 0; k1 < 15; k1++){
            float px = __shfl_xor_sync(0xffffffffu, B[k1].x, h);
            float py = __shfl_xor_sync(0xffffffffu, B[k1].y, h);
            float2 nv = make_float2(px + sgn*B[k1].x, py + sgn*B[k1].y);
            B[k1] = cmul(nv, tw);
        }
    }

    // lane l holds Z[k1 + 15*bitrev5(l)]
    int s = ((l&1)<<4) | ((l&2)<<2) | (l&4) | ((l&8)>>2) | ((l&16)>>4);
    float2* Z = sZ[w];
    #pragma unroll
    for (int k1 = 0; k1 < 15; k1++) Z[15*s + k1] = B[k1];
    __syncwarp();

    // ---- real-FFT recombination + spec write + mag
    float* mg = smag[w];
    float2* out2 = (float2*)out;
    size_t orow = (size_t)t * FREQ;
    for (int k = l; k <= 480; k += 32){
        float2 Zk = Z[(k == 480) ? 0 : k];
        float2 Zc = Z[(480 - k) % 480]; Zc.y = -Zc.y;
        float2 E = make_float2(0.5f*(Zk.x + Zc.x), 0.5f*(Zk.y + Zc.y));
        float2 D = make_float2(Zk.x - Zc.x, Zk.y - Zc.y);
        float2 O = make_float2(0.5f * D.y, -0.5f * D.x);
        float2 X = cadd(E, cmul(g_rec[k], O));
        X.x *= WNORM_F; X.y *= WNORM_F;
        out2[orow + k] = X;
        float m2 = X.x*X.x + X.y*X.y;
        mg[k] = m2;
        if (k < NB_DF) g_mag[(size_t)t * NB_DF + k] = sqrtf(m2);
    }
    __syncwarp();

    // ---- erb bands
    {
        int st = c_bandOff[l], n = c_bandCnt[l];
        float acc = 0.0f;
        for (int q = 0; q < n; q++) acc += mg[st + q];
        g_erb[(size_t)t * NB_ERB + l] = 10.0f * log10f(acc / (float)n + 1e-10f);
    }
}

// ---------------- fused chunked scans ----------------
__global__ void pass1(int T){
    int w = blockIdx.x * blockDim.x + threadIdx.x;
    int len = T / CHUNKS;
    int totE = CHUNKS * NB_ERB;
    if (w < totE){
        int ch = w % NB_ERB, c = w / NB_ERB;
        const float* x = g_erb + (size_t)c * len * NB_ERB + ch;
        float s = 0.0f;
        for (int i = 0; i < len; i++) s = ALPHA_F * s + ONE_MINUS_ALPHA * x[i * NB_ERB];
        g_carryE[c * NB_ERB + ch] = s;
    } else if (w < totE + CHUNKS * NB_DF){
        int w2 = w - totE;
        int ch = w2 % NB_DF, c = w2 / NB_DF;
        const float* x = g_mag + (size_t)c * len * NB_DF + ch;
        float u = 0.0f;
        for (int i = 0; i < len; i++) u = ALPHA_F * u + ONE_MINUS_ALPHA * x[i * NB_DF];
        g_carryS[c * NB_DF + ch] = u;
    }
}

// parallel affine scan across chunks: one block per channel (128 blocks x 1024 thr)
// chunk map: s -> m*s + carry_c ; exclusive scan composition applied to s0
__global__ __launch_bounds__(CHUNKS) void pass2(int T){
    __shared__ float sa[CHUNKS];
    __shared__ float sb[CHUNKS];
    int ch = blockIdx.x;          // 0..127 ; <32 erb, else df
    int c  = threadIdx.x;
    int len = T / CHUNKS;
    float m = __powf(ALPHA_F, (float)len);
    bool isErb = (ch < NB_ERB);
    int cc = isErb ? ch : (ch - NB_ERB);
    float carry = isErb ? g_carryE[c * NB_ERB + cc] : g_carryS[c * NB_DF + cc];

    float a = m, b = carry;        // inclusive element
    sa[c] = a; sb[c] = b;
    __syncthreads();
    #pragma unroll
    for (int off = 1; off < CHUNKS; off <<= 1){
        float pa = 0.f, pb = 0.f;
        if (c >= off){ pa = sa[c - off]; pb = sb[c - off]; }
        __syncthreads();
        if (c >= off){
            // right-compose: (pa,pb) then (a,b):  a' = a*pa, b' = a*pb + b
            b = a * pb + b;
            a = a * pa;
        }
        sa[c] = a; sb[c] = b;
        __syncthreads();
    }
    // exclusive: state before chunk c
    float Aex = (c == 0) ? 1.f : sa[c-1];
    float Bex = (c == 0) ? 0.f : sb[c-1];
    if (isErb){
        float s0 = -60.0f - 30.0f * (float)cc / 31.0f;
        g_inE[c * NB_ERB + cc] = Aex * s0 + Bex;
    } else {
        float u0 = 0.001f - 0.0009f * (float)cc / 95.0f;
        g_inS[c * NB_DF + cc] = Aex * u0 + Bex;
    }
}

__global__ void pass3(float* __restrict__ out, int T){
    int w = blockIdx.x * blockDim.x + threadIdx.x;
    int len = T / CHUNKS;
    int totE = CHUNKS * NB_ERB;
    if (w < totE){
        int ch = w % NB_ERB, c = w / NB_ERB;
        size_t erb_off = (size_t)T * 962;
        const float* x = g_erb + (size_t)c * len * NB_ERB + ch;
        float* o = out + erb_off + (size_t)c * len * NB_ERB + ch;
        float s = g_inE[c * NB_ERB + ch];
        for (int i = 0; i < len; i++){
            float xv = x[i * NB_ERB];
            s = ALPHA_F * s + ONE_MINUS_ALPHA * xv;
            o[i * NB_ERB] = (xv - s) * 0.025f;
        }
    } else if (w < totE + CHUNKS * NB_DF){
        int w2 = w - totE;
        int ch = w2 % NB_DF, c = w2 / NB_DF;
        size_t sf_off = (size_t)T * 962 + (size_t)T * NB_ERB;
        const float* mgp = g_mag + (size_t)c * len * NB_DF + ch;
        const float* sp = out + (size_t)c * len * 962 + 2 * ch;
        float* o = out + sf_off + (size_t)c * len * 192 + 2 * ch;
        float u = g_inS[c * NB_DF + ch];
        for (int i = 0; i < len; i++){
            u = ALPHA_F * u + ONE_MINUS_ALPHA * mgp[i * NB_DF];
            float r = rsqrtf(u);
            o[i * 192]     = sp[i * 962]     * r;
            o[i * 192 + 1] = sp[i * 962 + 1] * r;
        }
    }
}

// ---------------- launch ----------------
extern "C" void kernel_launch(void* const* d_in, const int* in_sizes, int n_in,
                              void* d_out, int out_size){
    const float* audio = (const float*)d_in[0];
    float* out = (float*)d_out;
    int T = in_sizes[0] / FRAME;
    if (T > T_MAX) T = T_MAX;
    int scanThreads = CHUNKS * (NB_ERB + NB_DF);

    init_tables<<<8, 256>>>();
    fft_kernel<<<(T + 3) / 4, 128>>>(audio, out, T);
    pass1<<<(scanThreads + 255) / 256, 256>>>(T);
    pass2<<<NB_ERB + NB_DF, CHUNKS>>>(T);
    pass3<<<(scanThreads + 255) / 256, 256>>>(out, T);
}